// round 11
// baseline (speedup 1.0000x reference)
#include <cuda_runtime.h>
#include <math.h>

// Problem dims (fixed by reference)
#define BB 8
#define TT 2048
#define DD 1024
#define HD 64
#define MM 64
#define SSZ (TT + MM)          // 2112 keys/values per batch
#define BT (BB * TT)           // 16384 query rows total

// d^-0.5 * log2(e): logits produced directly in log2 domain
#define SCALE_Q 0.18033688011112042f

// Scratch (allocation-free rule: __device__ globals)
__device__ float g_q[BT * HD];          // prescaled by d^-0.5*log2e
__device__ float g_k[BB * SSZ * HD];
__device__ float g_v[BB * SSZ * HD];

// ---------------------------------------------------------------------------
// Helpers
// ---------------------------------------------------------------------------
__device__ __forceinline__ unsigned tf32u(float x) {
    unsigned u;
    asm("cvt.rna.tf32.f32 %0, %1;" : "=r"(u) : "f"(x));
    return u;
}
__device__ __forceinline__ float tf32r(float x) {
    return __uint_as_float(tf32u(x));
}
__device__ __forceinline__ void mma8(float* c,
                                     unsigned a0, unsigned a1, unsigned a2, unsigned a3,
                                     unsigned b0, unsigned b1) {
    asm volatile(
        "mma.sync.aligned.m16n8k8.row.col.f32.tf32.tf32.f32 "
        "{%0,%1,%2,%3},{%4,%5,%6,%7},{%8,%9},{%0,%1,%2,%3};"
        : "+f"(c[0]), "+f"(c[1]), "+f"(c[2]), "+f"(c[3])
        : "r"(a0), "r"(a1), "r"(a2), "r"(a3), "r"(b0), "r"(b1));
}

// 2^y via MUFU (single instruction, separate pipe). rel err ~1e-6.
__device__ __forceinline__ float exp2a(float y) {
    float r;
    asm("ex2.approx.f32 %0, %1;" : "=f"(r) : "f"(y));
    return r;
}

__device__ __forceinline__ void cp16(void* smem_dst, const void* gmem_src) {
    unsigned s = (unsigned)__cvta_generic_to_shared(smem_dst);
    asm volatile("cp.async.cg.shared.global [%0], [%1], 16;"
                 :: "r"(s), "l"(gmem_src));
}
#define CP_COMMIT() asm volatile("cp.async.commit_group;" ::: "memory")
#define CP_WAIT0()  asm volatile("cp.async.wait_group 0;" ::: "memory")

// ---------------------------------------------------------------------------
// Kernel 1: layernorm(c_emb) -> broadcast (tf32-rounded) into g_k/g_v tails
// ---------------------------------------------------------------------------
__global__ void ln_kernel(const float* __restrict__ c_emb,
                          const float* __restrict__ gamma,
                          const float* __restrict__ beta) {
    int m = blockIdx.x;
    int t = threadIdx.x;
    __shared__ float red[64];

    float v = c_emb[m * HD + t];
    red[t] = v;
    __syncthreads();
    for (int off = 32; off > 0; off >>= 1) {
        if (t < off) red[t] += red[t + off];
        __syncthreads();
    }
    float mu = red[0] * (1.0f / HD);
    __syncthreads();
    float dv = v - mu;
    red[t] = dv * dv;
    __syncthreads();
    for (int off = 32; off > 0; off >>= 1) {
        if (t < off) red[t] += red[t + off];
        __syncthreads();
    }
    float var = red[0] * (1.0f / HD);
    float y = tf32r(dv * rsqrtf(var + 1e-5f) * gamma[t] + beta[t]);

    #pragma unroll
    for (int b = 0; b < BB; b++) {
        int idx = ((b * SSZ) + TT + m) * HD + t;
        g_k[idx] = y;
        g_v[idx] = y;
    }
}

// ---------------------------------------------------------------------------
// Kernel 2: fused QKV projection via tf32 mma + register prefetch (as R7).
// ---------------------------------------------------------------------------
#define XS_ST 36
#define WS_ST 196
__global__ __launch_bounds__(256) void qkv_kernel(
    const float* __restrict__ x,
    const float* __restrict__ Wq,
    const float* __restrict__ Wk,
    const float* __restrict__ Wv) {

    __shared__ float xs[64][XS_ST];
    __shared__ float ws[32][WS_ST];

    int tid = threadIdx.x;
    int lane = tid & 31;
    int wid = tid >> 5;
    int wm = wid & 3;
    int wn = wid >> 2;
    int g = lane >> 2;
    int t = lane & 3;
    int row0 = blockIdx.x * 64;

    float acc[12][4];
    #pragma unroll
    for (int n = 0; n < 12; n++)
        #pragma unroll
        for (int i = 0; i < 4; i++) acc[n][i] = 0.0f;

    float4 xr[2], wqr[2], wkr[2], wvr[2];

    #pragma unroll
    for (int i = 0; i < 2; i++) {
        int idx = tid + i * 256;
        int r = idx >> 3;
        int q = idx & 7;
        xr[i] = *(const float4*)&x[(size_t)(row0 + r) * DD + q * 4];
    }
    #pragma unroll
    for (int i = 0; i < 2; i++) {
        int idx = tid + i * 256;
        int r = idx >> 4;
        int q = idx & 15;
        wqr[i] = *(const float4*)&Wq[(size_t)r * HD + q * 4];
        wkr[i] = *(const float4*)&Wk[(size_t)r * HD + q * 4];
        wvr[i] = *(const float4*)&Wv[(size_t)r * HD + q * 4];
    }

    for (int k0 = 0; k0 < DD; k0 += 32) {
        #pragma unroll
        for (int i = 0; i < 2; i++) {
            int idx = tid + i * 256;
            int r = idx >> 3;
            int q = idx & 7;
            xs[r][q * 4 + 0] = tf32r(xr[i].x);
            xs[r][q * 4 + 1] = tf32r(xr[i].y);
            xs[r][q * 4 + 2] = tf32r(xr[i].z);
            xs[r][q * 4 + 3] = tf32r(xr[i].w);
        }
        #pragma unroll
        for (int i = 0; i < 2; i++) {
            int idx = tid + i * 256;
            int r = idx >> 4;
            int q = idx & 15;
            int c = q * 4;
            ws[r][c + 0] = tf32r(wqr[i].x); ws[r][c + 1] = tf32r(wqr[i].y);
            ws[r][c + 2] = tf32r(wqr[i].z); ws[r][c + 3] = tf32r(wqr[i].w);
            ws[r][64 + c + 0] = tf32r(wkr[i].x); ws[r][64 + c + 1] = tf32r(wkr[i].y);
            ws[r][64 + c + 2] = tf32r(wkr[i].z); ws[r][64 + c + 3] = tf32r(wkr[i].w);
            ws[r][128 + c + 0] = tf32r(wvr[i].x); ws[r][128 + c + 1] = tf32r(wvr[i].y);
            ws[r][128 + c + 2] = tf32r(wvr[i].z); ws[r][128 + c + 3] = tf32r(wvr[i].w);
        }
        __syncthreads();

        if (k0 + 32 < DD) {
            int kn = k0 + 32;
            #pragma unroll
            for (int i = 0; i < 2; i++) {
                int idx = tid + i * 256;
                int r = idx >> 3;
                int q = idx & 7;
                xr[i] = *(const float4*)&x[(size_t)(row0 + r) * DD + kn + q * 4];
            }
            #pragma unroll
            for (int i = 0; i < 2; i++) {
                int idx = tid + i * 256;
                int r = idx >> 4;
                int q = idx & 15;
                wqr[i] = *(const float4*)&Wq[(size_t)(kn + r) * HD + q * 4];
                wkr[i] = *(const float4*)&Wk[(size_t)(kn + r) * HD + q * 4];
                wvr[i] = *(const float4*)&Wv[(size_t)(kn + r) * HD + q * 4];
            }
        }

        #pragma unroll
        for (int kk = 0; kk < 4; kk++) {
            int kb = kk * 8;
            unsigned a0 = __float_as_uint(xs[wm * 16 + g][kb + t]);
            unsigned a1 = __float_as_uint(xs[wm * 16 + g + 8][kb + t]);
            unsigned a2 = __float_as_uint(xs[wm * 16 + g][kb + t + 4]);
            unsigned a3 = __float_as_uint(xs[wm * 16 + g + 8][kb + t + 4]);
            #pragma unroll
            for (int n = 0; n < 12; n++) {
                int nc = wn * 96 + n * 8;
                unsigned b0 = __float_as_uint(ws[kb + t][nc + g]);
                unsigned b1 = __float_as_uint(ws[kb + t + 4][nc + g]);
                mma8(acc[n], a0, a1, a2, a3, b0, b1);
            }
        }
        __syncthreads();
    }

    int r0 = row0 + wm * 16 + g;
    #pragma unroll
    for (int n = 0; n < 12; n++) {
        int nc = wn * 96 + n * 8;
        int mat = nc >> 6;
        int lc = (nc & 63) + 2 * t;
        #pragma unroll
        for (int h = 0; h < 2; h++) {
            int r = r0 + h * 8;
            float v0 = acc[n][h * 2 + 0];
            float v1 = acc[n][h * 2 + 1];
            if (mat == 0) {
                float2 o = make_float2(tf32r(v0 * SCALE_Q), tf32r(v1 * SCALE_Q));
                *(float2*)&g_q[(size_t)r * HD + lc] = o;
            } else {
                int b = r >> 11;
                int rr = r & 2047;
                float2 o = make_float2(tf32r(v0), tf32r(v1));
                if (mat == 1) *(float2*)&g_k[((size_t)b * SSZ + rr) * HD + lc] = o;
                else          *(float2*)&g_v[((size_t)b * SSZ + rr) * HD + lc] = o;
            }
        }
    }
}

// ---------------------------------------------------------------------------
// Kernel 3: flash attention v4 — intra-CTA split-KV, two 4-warp families.
// 256 threads. Family 0 (warps 0-3) processes even 64-key tiles, family 1
// (warps 4-7) odd tiles; both cover all 128 query rows (warp tile 32x64,
// B-frags reused across 2 M-tiles). K/V streamed as double-buffered 128-row
// pairs. Q fragments live in registers; each family has a private P buffer
// (family 0's aliases the Q staging area). Partial softmaxes merged in the
// epilogue via standard split-KV rescaling.
// ---------------------------------------------------------------------------
#define TP2 68                               // stride = 4 (mod 32)
#define PAIRB (128 * TP2)                    // one 128-row K or V pair buffer
#define OFF_P0 0
#define OFF_P1 (128 * TP2)
#define OFF_K  (2 * 128 * TP2)
#define OFF_V  (OFF_K + 2 * PAIRB)
#define OFF_M1 (OFF_V + 2 * PAIRB)
#define OFF_L1 (OFF_M1 + 128)
#define ATTN_SMEM_FLOATS (OFF_L1 + 128)
#define ATTN_SMEM_BYTES  (ATTN_SMEM_FLOATS * 4)

__global__ __launch_bounds__(256, 1) void attn_kernel(float* __restrict__ out) {
    extern __shared__ float sm[];
    float* p0   = sm + OFF_P0;               // Q staging, then fam0 P
    float* p1   = sm + OFF_P1;               // fam1 P, then fam1 acc publish
    float* kbuf = sm + OFF_K;                // 2 x [128][TP2]
    float* vbuf = sm + OFF_V;                // 2 x [128][TP2]
    float* m1s  = sm + OFF_M1;               // [128]
    float* l1s  = sm + OFF_L1;               // [128]

    int tid = threadIdx.x;
    int lane = tid & 31;
    int w = tid >> 5;
    int fam = w >> 2;                        // 0: even tiles, 1: odd tiles
    int wf = w & 3;                          // row group within family
    int g = lane >> 2;
    int t = lane & 3;
    int b = blockIdx.y;
    int q0 = blockIdx.x * 128;
    int r0 = wf * 32;
    float* pfam = fam ? p1 : p0;

    // Prologue: async-load K/V pair 0 (tiles 0,1) into buffer 0
    #pragma unroll
    for (int it = 0; it < 8; it++) {
        int idx = tid + it * 256;
        int r = idx >> 4;
        int q = idx & 15;
        size_t src = ((size_t)b * SSZ + r) * HD + q * 4;
        cp16(kbuf + r * TP2 + q * 4, &g_k[src]);
        cp16(vbuf + r * TP2 + q * 4, &g_v[src]);
    }
    CP_COMMIT();

    // Stage Q 128x64 into p0 (coalesced), then hoist fragments to registers
    #pragma unroll
    for (int it = 0; it < 8; it++) {
        int idx = tid + it * 256;
        int r = idx >> 4;
        int q = idx & 15;
        float4 v = *(const float4*)&g_q[((size_t)b * TT + q0 + r) * HD + q * 4];
        *(float4*)&p0[r * TP2 + q * 4] = v;
    }
    __syncthreads();
    unsigned qf[2][8][4];
    #pragma unroll
    for (int h = 0; h < 2; h++) {
        int rr = r0 + h * 16 + g;
        #pragma unroll
        for (int kk = 0; kk < 8; kk++) {
            int kb = kk * 8;
            qf[h][kk][0] = __float_as_uint(p0[rr * TP2 + kb + t]);
            qf[h][kk][1] = __float_as_uint(p0[(rr + 8) * TP2 + kb + t]);
            qf[h][kk][2] = __float_as_uint(p0[rr * TP2 + kb + t + 4]);
            qf[h][kk][3] = __float_as_uint(p0[(rr + 8) * TP2 + kb + t + 4]);
        }
    }
    // p0 rows become fam0's P buffer after the first loop-top barrier

    float m[4] = {-1e30f, -1e30f, -1e30f, -1e30f};
    float l[4] = {0.0f, 0.0f, 0.0f, 0.0f};
    float acc[2][8][4];
    #pragma unroll
    for (int h = 0; h < 2; h++)
        #pragma unroll
        for (int n = 0; n < 8; n++)
            #pragma unroll
            for (int i = 0; i < 4; i++) acc[h][n][i] = 0.0f;

    for (int j = 0; j < 17; j++) {           // 17 pairs cover 33 tiles
        CP_WAIT0();
        __syncthreads();   // pair j visible; qf loads / prev iter done

        if (j < 16) {
            int base = 128 * (j + 1);
            float* kb_ = kbuf + ((j + 1) & 1) * PAIRB;
            float* vb_ = vbuf + ((j + 1) & 1) * PAIRB;
            #pragma unroll
            for (int it = 0; it < 8; it++) {
                int idx = tid + it * 256;
                int r = idx >> 4;
                int q = idx & 15;
                if (base + r < SSZ) {
                    size_t src = ((size_t)b * SSZ + base + r) * HD + q * 4;
                    cp16(kb_ + r * TP2 + q * 4, &g_k[src]);
                    cp16(vb_ + r * TP2 + q * 4, &g_v[src]);
                }
            }
            CP_COMMIT();
        }

        bool active = (fam == 0) || (j < 16);   // tile 2j+1 exists only j<16
        const float* kcur = kbuf + (j & 1) * PAIRB + fam * 64 * TP2;
        const float* vcur = vbuf + (j & 1) * PAIRB + fam * 64 * TP2;

        if (active) {
            // Phase A: S = Q * K^T  (warp: 32 rows x 64 cols)
            float sc[2][8][4];
            #pragma unroll
            for (int h = 0; h < 2; h++)
                #pragma unroll
                for (int n = 0; n < 8; n++)
                    #pragma unroll
                    for (int i = 0; i < 4; i++) sc[h][n][i] = 0.0f;
            #pragma unroll
            for (int kk = 0; kk < 8; kk++) {
                int kb = kk * 8;
                #pragma unroll
                for (int n = 0; n < 8; n++) {
                    unsigned b0 = __float_as_uint(kcur[(n * 8 + g) * TP2 + kb + t]);
                    unsigned b1 = __float_as_uint(kcur[(n * 8 + g) * TP2 + kb + t + 4]);
                    mma8(sc[0][n], qf[0][kk][0], qf[0][kk][1], qf[0][kk][2], qf[0][kk][3], b0, b1);
                    mma8(sc[1][n], qf[1][kk][0], qf[1][kk][1], qf[1][kk][2], qf[1][kk][3], b0, b1);
                }
            }

            // Softmax (registers + shfl; exp on MUFU), then stash P
            #pragma unroll
            for (int h = 0; h < 2; h++) {
                float mx0 = -1e30f, mx1 = -1e30f;
                #pragma unroll
                for (int n = 0; n < 8; n++) {
                    mx0 = fmaxf(mx0, fmaxf(sc[h][n][0], sc[h][n][1]));
                    mx1 = fmaxf(mx1, fmaxf(sc[h][n][2], sc[h][n][3]));
                }
                mx0 = fmaxf(mx0, __shfl_xor_sync(0xffffffffu, mx0, 1));
                mx0 = fmaxf(mx0, __shfl_xor_sync(0xffffffffu, mx0, 2));
                mx1 = fmaxf(mx1, __shfl_xor_sync(0xffffffffu, mx1, 1));
                mx1 = fmaxf(mx1, __shfl_xor_sync(0xffffffffu, mx1, 2));
                float mn0 = fmaxf(m[2 * h], mx0);
                float mn1 = fmaxf(m[2 * h + 1], mx1);
                float f0 = exp2a(m[2 * h] - mn0);
                float f1 = exp2a(m[2 * h + 1] - mn1);
                float s0 = 0.0f, s1 = 0.0f;
                #pragma unroll
                for (int n = 0; n < 8; n++) {
                    sc[h][n][0] = tf32r(exp2a(sc[h][n][0] - mn0)); s0 += sc[h][n][0];
                    sc[h][n][1] = tf32r(exp2a(sc[h][n][1] - mn0)); s0 += sc[h][n][1];
                    sc[h][n][2] = tf32r(exp2a(sc[h][n][2] - mn1)); s1 += sc[h][n][2];
                    sc[h][n][3] = tf32r(exp2a(sc[h][n][3] - mn1)); s1 += sc[h][n][3];
                }
                s0 += __shfl_xor_sync(0xffffffffu, s0, 1);
                s0 += __shfl_xor_sync(0xffffffffu, s0, 2);
                s1 += __shfl_xor_sync(0xffffffffu, s1, 1);
                s1 += __shfl_xor_sync(0xffffffffu, s1, 2);
                l[2 * h]     = l[2 * h] * f0 + s0;
                l[2 * h + 1] = l[2 * h + 1] * f1 + s1;
                m[2 * h]     = mn0;
                m[2 * h + 1] = mn1;
                #pragma unroll
                for (int n = 0; n < 8; n++) {
                    acc[h][n][0] *= f0; acc[h][n][1] *= f0;
                    acc[h][n][2] *= f1; acc[h][n][3] *= f1;
                }
                int rr = r0 + h * 16 + g;
                #pragma unroll
                for (int n = 0; n < 8; n++) {
                    *(float2*)&pfam[rr * TP2 + n * 8 + 2 * t] =
                        make_float2(sc[h][n][0], sc[h][n][1]);
                    *(float2*)&pfam[(rr + 8) * TP2 + n * 8 + 2 * t] =
                        make_float2(sc[h][n][2], sc[h][n][3]);
                }
            }
            __syncwarp();

            // Phase C: O += P * V  (warp: 32 rows x 64 cols)
            #pragma unroll
            for (int kk = 0; kk < 8; kk++) {
                int kb = kk * 8;
                unsigned a[2][4];
                #pragma unroll
                for (int h = 0; h < 2; h++) {
                    int rr = r0 + h * 16 + g;
                    a[h][0] = __float_as_uint(pfam[rr * TP2 + kb + t]);
                    a[h][1] = __float_as_uint(pfam[(rr + 8) * TP2 + kb + t]);
                    a[h][2] = __float_as_uint(pfam[rr * TP2 + kb + t + 4]);
                    a[h][3] = __float_as_uint(pfam[(rr + 8) * TP2 + kb + t + 4]);
                }
                #pragma unroll
                for (int n = 0; n < 8; n++) {
                    unsigned b0 = __float_as_uint(vcur[(kb + t) * TP2 + n * 8 + g]);
                    unsigned b1 = __float_as_uint(vcur[(kb + t + 4) * TP2 + n * 8 + g]);
                    mma8(acc[0][n], a[0][0], a[0][1], a[0][2], a[0][3], b0, b1);
                    mma8(acc[1][n], a[1][0], a[1][1], a[1][2], a[1][3], b0, b1);
                }
            }
        }
        // next-iter __syncthreads guards K/V buffer and P-slice reuse
    }

    // ---- Split-KV merge epilogue ----
    __syncthreads();   // all compute done; P buffers free for publishing
    if (fam == 1) {
        #pragma unroll
        for (int h = 0; h < 2; h++) {
            int rr = r0 + h * 16 + g;
            #pragma unroll
            for (int n = 0; n < 8; n++) {
                *(float2*)&p1[rr * TP2 + n * 8 + 2 * t] =
                    make_float2(acc[h][n][0], acc[h][n][1]);
                *(float2*)&p1[(rr + 8) * TP2 + n * 8 + 2 * t] =
                    make_float2(acc[h][n][2], acc[h][n][3]);
            }
            if (t == 0) {
                m1s[rr]     = m[2 * h];     l1s[rr]     = l[2 * h];
                m1s[rr + 8] = m[2 * h + 1]; l1s[rr + 8] = l[2 * h + 1];
            }
        }
    }
    __syncthreads();
    if (fam == 0) {
        #pragma unroll
        for (int h = 0; h < 2; h++) {
            int ra = r0 + h * 16 + g;
            int rb = ra + 8;
            float mB0 = m1s[ra], lB0 = l1s[ra];
            float mt0 = fmaxf(m[2 * h], mB0);
            float a0 = exp2a(m[2 * h] - mt0);
            float b0c = exp2a(mB0 - mt0);
            float inv0 = 1.0f / (l[2 * h] * a0 + lB0 * b0c);
            float mB1 = m1s[rb], lB1 = l1s[rb];
            float mt1 = fmaxf(m[2 * h + 1], mB1);
            float a1 = exp2a(m[2 * h + 1] - mt1);
            float b1c = exp2a(mB1 - mt1);
            float inv1 = 1.0f / (l[2 * h + 1] * a1 + lB1 * b1c);
            #pragma unroll
            for (int n = 0; n < 8; n++) {
                int col = n * 8 + 2 * t;
                float2 o1 = *(float2*)&p1[ra * TP2 + col];
                float2 o2 = *(float2*)&p1[rb * TP2 + col];
                *(float2*)&out[((size_t)b * TT + q0 + ra) * HD + col] =
                    make_float2((acc[h][n][0] * a0 + o1.x * b0c) * inv0,
                                (acc[h][n][1] * a0 + o1.y * b0c) * inv0);
                *(float2*)&out[((size_t)b * TT + q0 + rb) * HD + col] =
                    make_float2((acc[h][n][2] * a1 + o2.x * b1c) * inv1,
                                (acc[h][n][3] * a1 + o2.y * b1c) * inv1);
            }
        }
    }
}

// ---------------------------------------------------------------------------
extern "C" void kernel_launch(void* const* d_in, const int* in_sizes, int n_in,
                              void* d_out, int out_size) {
    const float* x      = (const float*)d_in[0];  // [8,2048,1024]
    const float* c_emb  = (const float*)d_in[1];  // [64,64]
    const float* Wq     = (const float*)d_in[2];  // [1024,64]
    const float* Wk     = (const float*)d_in[3];
    const float* Wv     = (const float*)d_in[4];
    const float* gamma  = (const float*)d_in[5];  // [64]
    const float* beta   = (const float*)d_in[6];  // [64]
    float* out          = (float*)d_out;          // [8,2048,64]

    (void)in_sizes; (void)n_in; (void)out_size;

    cudaFuncSetAttribute(attn_kernel,
                         cudaFuncAttributeMaxDynamicSharedMemorySize,
                         ATTN_SMEM_BYTES);

    ln_kernel<<<MM, 64>>>(c_emb, gamma, beta);
    qkv_kernel<<<BT / 64, 256>>>(x, Wq, Wk, Wv);
    dim3 agrid(TT / 128, BB);
    attn_kernel<<<agrid, 256, ATTN_SMEM_BYTES>>>(out);
}

// round 12
// speedup vs baseline: 1.2490x; 1.2490x over previous
#include <cuda_runtime.h>
#include <math.h>

// Problem dims (fixed by reference)
#define BB 8
#define TT 2048
#define DD 1024
#define HD 64
#define MM 64
#define SSZ (TT + MM)          // 2112 keys/values per batch
#define BT (BB * TT)           // 16384 query rows total

// d^-0.5 * log2(e): logits produced directly in log2 domain
#define SCALE_Q 0.18033688011112042f

// Scratch (allocation-free rule: __device__ globals)
__device__ float g_q[BT * HD];          // prescaled by d^-0.5*log2e
__device__ float g_k[BB * SSZ * HD];
__device__ float g_v[BB * SSZ * HD];

// ---------------------------------------------------------------------------
// Helpers
// ---------------------------------------------------------------------------
__device__ __forceinline__ unsigned tf32u(float x) {
    unsigned u;
    asm("cvt.rna.tf32.f32 %0, %1;" : "=r"(u) : "f"(x));
    return u;
}
__device__ __forceinline__ float tf32r(float x) {
    return __uint_as_float(tf32u(x));
}
__device__ __forceinline__ void mma8(float* c,
                                     unsigned a0, unsigned a1, unsigned a2, unsigned a3,
                                     unsigned b0, unsigned b1) {
    asm volatile(
        "mma.sync.aligned.m16n8k8.row.col.f32.tf32.tf32.f32 "
        "{%0,%1,%2,%3},{%4,%5,%6,%7},{%8,%9},{%0,%1,%2,%3};"
        : "+f"(c[0]), "+f"(c[1]), "+f"(c[2]), "+f"(c[3])
        : "r"(a0), "r"(a1), "r"(a2), "r"(a3), "r"(b0), "r"(b1));
}

// 2^y via MUFU (single instruction, separate pipe). rel err ~1e-6.
__device__ __forceinline__ float exp2a(float y) {
    float r;
    asm("ex2.approx.f32 %0, %1;" : "=f"(r) : "f"(y));
    return r;
}

__device__ __forceinline__ void cp16(void* smem_dst, const void* gmem_src) {
    unsigned s = (unsigned)__cvta_generic_to_shared(smem_dst);
    asm volatile("cp.async.cg.shared.global [%0], [%1], 16;"
                 :: "r"(s), "l"(gmem_src));
}
#define CP_COMMIT() asm volatile("cp.async.commit_group;" ::: "memory")
#define CP_WAIT0()  asm volatile("cp.async.wait_group 0;" ::: "memory")

// ---------------------------------------------------------------------------
// Kernel 1: layernorm(c_emb) -> broadcast (tf32-rounded) into g_k/g_v tails
// ---------------------------------------------------------------------------
__global__ void ln_kernel(const float* __restrict__ c_emb,
                          const float* __restrict__ gamma,
                          const float* __restrict__ beta) {
    int m = blockIdx.x;
    int t = threadIdx.x;
    __shared__ float red[64];

    float v = c_emb[m * HD + t];
    red[t] = v;
    __syncthreads();
    for (int off = 32; off > 0; off >>= 1) {
        if (t < off) red[t] += red[t + off];
        __syncthreads();
    }
    float mu = red[0] * (1.0f / HD);
    __syncthreads();
    float dv = v - mu;
    red[t] = dv * dv;
    __syncthreads();
    for (int off = 32; off > 0; off >>= 1) {
        if (t < off) red[t] += red[t + off];
        __syncthreads();
    }
    float var = red[0] * (1.0f / HD);
    float y = tf32r(dv * rsqrtf(var + 1e-5f) * gamma[t] + beta[t]);

    #pragma unroll
    for (int b = 0; b < BB; b++) {
        int idx = ((b * SSZ) + TT + m) * HD + t;
        g_k[idx] = y;
        g_v[idx] = y;
    }
}

// ---------------------------------------------------------------------------
// Kernel 2: fused QKV projection v2. Tile 128(M) x 192(N), K-chunk 32;
// grid = 128 CTAs (single wave). 8 warps as 4(M: 32 rows) x 2(N: 96 cols);
// B-fragments reused across 2 M-tiles (halved smem B traffic vs v1).
// Register prefetch of the next K-chunk. Per-output accumulation order
// identical to v1 -> bit-identical results.
// ---------------------------------------------------------------------------
#define XS_ST 36
#define WS_ST 196
__global__ __launch_bounds__(256) void qkv_kernel(
    const float* __restrict__ x,
    const float* __restrict__ Wq,
    const float* __restrict__ Wk,
    const float* __restrict__ Wv) {

    __shared__ float xs[128][XS_ST];     // 18.4 KB
    __shared__ float ws[32][WS_ST];      // 25.1 KB

    int tid = threadIdx.x;
    int lane = tid & 31;
    int wid = tid >> 5;
    int wm = wid & 3;                    // 32-row group
    int wn = wid >> 2;                   // 96-col group
    int g = lane >> 2;
    int t = lane & 3;
    int row0 = blockIdx.x * 128;

    float acc[2][12][4];
    #pragma unroll
    for (int h = 0; h < 2; h++)
        #pragma unroll
        for (int n = 0; n < 12; n++)
            #pragma unroll
            for (int i = 0; i < 4; i++) acc[h][n][i] = 0.0f;

    float4 xr[4], wqr[2], wkr[2], wvr[2];

    // Load chunk k0 = 0
    #pragma unroll
    for (int i = 0; i < 4; i++) {
        int idx = tid + i * 256;         // 1024 quads = 128x32 floats
        int r = idx >> 3;
        int q = idx & 7;
        xr[i] = *(const float4*)&x[(size_t)(row0 + r) * DD + q * 4];
    }
    #pragma unroll
    for (int i = 0; i < 2; i++) {
        int idx = tid + i * 256;
        int r = idx >> 4;
        int q = idx & 15;
        wqr[i] = *(const float4*)&Wq[(size_t)r * HD + q * 4];
        wkr[i] = *(const float4*)&Wk[(size_t)r * HD + q * 4];
        wvr[i] = *(const float4*)&Wv[(size_t)r * HD + q * 4];
    }

    for (int k0 = 0; k0 < DD; k0 += 32) {
        // Store current chunk to smem (tf32-rounded)
        #pragma unroll
        for (int i = 0; i < 4; i++) {
            int idx = tid + i * 256;
            int r = idx >> 3;
            int q = idx & 7;
            xs[r][q * 4 + 0] = tf32r(xr[i].x);
            xs[r][q * 4 + 1] = tf32r(xr[i].y);
            xs[r][q * 4 + 2] = tf32r(xr[i].z);
            xs[r][q * 4 + 3] = tf32r(xr[i].w);
        }
        #pragma unroll
        for (int i = 0; i < 2; i++) {
            int idx = tid + i * 256;
            int r = idx >> 4;
            int q = idx & 15;
            int c = q * 4;
            ws[r][c + 0] = tf32r(wqr[i].x); ws[r][c + 1] = tf32r(wqr[i].y);
            ws[r][c + 2] = tf32r(wqr[i].z); ws[r][c + 3] = tf32r(wqr[i].w);
            ws[r][64 + c + 0] = tf32r(wkr[i].x); ws[r][64 + c + 1] = tf32r(wkr[i].y);
            ws[r][64 + c + 2] = tf32r(wkr[i].z); ws[r][64 + c + 3] = tf32r(wkr[i].w);
            ws[r][128 + c + 0] = tf32r(wvr[i].x); ws[r][128 + c + 1] = tf32r(wvr[i].y);
            ws[r][128 + c + 2] = tf32r(wvr[i].z); ws[r][128 + c + 3] = tf32r(wvr[i].w);
        }
        __syncthreads();

        // Prefetch next chunk (overlaps with mma below)
        if (k0 + 32 < DD) {
            int kn = k0 + 32;
            #pragma unroll
            for (int i = 0; i < 4; i++) {
                int idx = tid + i * 256;
                int r = idx >> 3;
                int q = idx & 7;
                xr[i] = *(const float4*)&x[(size_t)(row0 + r) * DD + kn + q * 4];
            }
            #pragma unroll
            for (int i = 0; i < 2; i++) {
                int idx = tid + i * 256;
                int r = idx >> 4;
                int q = idx & 15;
                wqr[i] = *(const float4*)&Wq[(size_t)(kn + r) * HD + q * 4];
                wkr[i] = *(const float4*)&Wk[(size_t)(kn + r) * HD + q * 4];
                wvr[i] = *(const float4*)&Wv[(size_t)(kn + r) * HD + q * 4];
            }
        }

        #pragma unroll
        for (int kk = 0; kk < 4; kk++) {
            int kb = kk * 8;
            unsigned a[2][4];
            #pragma unroll
            for (int h = 0; h < 2; h++) {
                int rr = wm * 32 + h * 16 + g;
                a[h][0] = __float_as_uint(xs[rr][kb + t]);
                a[h][1] = __float_as_uint(xs[rr + 8][kb + t]);
                a[h][2] = __float_as_uint(xs[rr][kb + t + 4]);
                a[h][3] = __float_as_uint(xs[rr + 8][kb + t + 4]);
            }
            #pragma unroll
            for (int n = 0; n < 12; n++) {
                int nc = wn * 96 + n * 8;
                unsigned b0 = __float_as_uint(ws[kb + t][nc + g]);
                unsigned b1 = __float_as_uint(ws[kb + t + 4][nc + g]);
                mma8(acc[0][n], a[0][0], a[0][1], a[0][2], a[0][3], b0, b1);
                mma8(acc[1][n], a[1][0], a[1][1], a[1][2], a[1][3], b0, b1);
            }
        }
        __syncthreads();
    }

    // Epilogue: scatter (tf32-rounded) into g_q (prescaled), g_k, g_v
    #pragma unroll
    for (int h = 0; h < 2; h++) {
        int r0 = row0 + wm * 32 + h * 16 + g;    // rows r0, r0+8
        #pragma unroll
        for (int n = 0; n < 12; n++) {
            int nc = wn * 96 + n * 8;
            int mat = nc >> 6;                   // 0=q, 1=k, 2=v
            int lc = (nc & 63) + 2 * t;
            #pragma unroll
            for (int hh = 0; hh < 2; hh++) {     // hh=0 -> r0, hh=1 -> r0+8
                int r = r0 + hh * 8;
                float v0 = acc[h][n][hh * 2 + 0];
                float v1 = acc[h][n][hh * 2 + 1];
                if (mat == 0) {
                    float2 o = make_float2(tf32r(v0 * SCALE_Q), tf32r(v1 * SCALE_Q));
                    *(float2*)&g_q[(size_t)r * HD + lc] = o;
                } else {
                    int b = r >> 11;
                    int rr = r & 2047;
                    float2 o = make_float2(tf32r(v0), tf32r(v1));
                    if (mat == 1) *(float2*)&g_k[((size_t)b * SSZ + rr) * HD + lc] = o;
                    else          *(float2*)&g_v[((size_t)b * SSZ + rr) * HD + lc] = o;
                }
            }
        }
    }
}

// ---------------------------------------------------------------------------
// Kernel 3: flash attention (R10 version, proven 182.2us). 128 queries/CTA,
// 4 warps x 32 rows each; B-fragments reused across 2 M-tiles; softmax exp
// on MUFU; S in registers; P in warp-private smem rows; 1 barrier per tile.
// ---------------------------------------------------------------------------
#define TP2 68                               // stride = 4 (mod 32)
#define KVB (64 * TP2)                       // one K or V buffer (floats)
#define ATTN_SMEM_FLOATS (2 * 128 * TP2 + 4 * KVB)
#define ATTN_SMEM_BYTES  (ATTN_SMEM_FLOATS * 4)

__global__ __launch_bounds__(128, 1) void attn_kernel(float* __restrict__ out) {
    extern __shared__ float sm[];
    float* qs = sm;                          // [128][TP2] Q (persistent)
    float* ps = sm + 128 * TP2;              // [128][TP2] P (warp-private rows)
    float* ks = sm + 2 * 128 * TP2;          // 2 x [64][TP2]
    float* vs = ks + 2 * KVB;                // 2 x [64][TP2]

    int tid = threadIdx.x;
    int lane = tid & 31;
    int w = tid >> 5;                        // warp id: rows w*32..w*32+31
    int g = lane >> 2;
    int t = lane & 3;
    int b = blockIdx.y;
    int q0 = blockIdx.x * 128;
    int r0 = w * 32;

    // Stage Q 128x64 (coalesced)
    #pragma unroll
    for (int i = 0; i < 16; i++) {
        int idx = tid + i * 128;
        int r = idx >> 4;
        int q = idx & 15;
        float4 v = *(const float4*)&g_q[((size_t)b * TT + q0 + r) * HD + q * 4];
        *(float4*)&qs[r * TP2 + q * 4] = v;
    }

    // Prologue: async-load K/V tile 0 into buffer 0
    #pragma unroll
    for (int it = 0; it < 8; it++) {
        int idx = tid + it * 128;
        int r = idx >> 4;
        int q = idx & 15;
        size_t src = ((size_t)b * SSZ + r) * HD + q * 4;
        cp16(ks + r * TP2 + q * 4, &g_k[src]);
        cp16(vs + r * TP2 + q * 4, &g_v[src]);
    }
    CP_COMMIT();

    // Row stats: h=0 -> rows r0+g, r0+g+8; h=1 -> rows r0+16+g, r0+16+g+8
    float m[4] = {-1e30f, -1e30f, -1e30f, -1e30f};
    float l[4] = {0.0f, 0.0f, 0.0f, 0.0f};
    float acc[2][8][4];
    #pragma unroll
    for (int h = 0; h < 2; h++)
        #pragma unroll
        for (int n = 0; n < 8; n++)
            #pragma unroll
            for (int i = 0; i < 4; i++) acc[h][n][i] = 0.0f;

    for (int ti = 0; ti < 33; ti++) {
        CP_WAIT0();
        __syncthreads();   // tile ti visible; everyone done with prev iter

        if (ti < 32) {
            int s0 = (ti + 1) * 64;
            float* kb_ = ks + ((ti + 1) & 1) * KVB;
            float* vb_ = vs + ((ti + 1) & 1) * KVB;
            #pragma unroll
            for (int it = 0; it < 8; it++) {
                int idx = tid + it * 128;
                int r = idx >> 4;
                int q = idx & 15;
                size_t src = ((size_t)b * SSZ + s0 + r) * HD + q * 4;
                cp16(kb_ + r * TP2 + q * 4, &g_k[src]);
                cp16(vb_ + r * TP2 + q * 4, &g_v[src]);
            }
            CP_COMMIT();
        }

        const float* kcur = ks + (ti & 1) * KVB;
        const float* vcur = vs + (ti & 1) * KVB;

        // Phase A: S = Q * K^T  (warp: 32 rows x 64 cols; K frags reused 2x)
        float sc[2][8][4];
        #pragma unroll
        for (int h = 0; h < 2; h++)
            #pragma unroll
            for (int n = 0; n < 8; n++)
                #pragma unroll
                for (int i = 0; i < 4; i++) sc[h][n][i] = 0.0f;
        #pragma unroll
        for (int kk = 0; kk < 8; kk++) {
            int kb = kk * 8;
            unsigned a[2][4];
            #pragma unroll
            for (int h = 0; h < 2; h++) {
                int rr = r0 + h * 16 + g;
                a[h][0] = __float_as_uint(qs[rr * TP2 + kb + t]);
                a[h][1] = __float_as_uint(qs[(rr + 8) * TP2 + kb + t]);
                a[h][2] = __float_as_uint(qs[rr * TP2 + kb + t + 4]);
                a[h][3] = __float_as_uint(qs[(rr + 8) * TP2 + kb + t + 4]);
            }
            #pragma unroll
            for (int n = 0; n < 8; n++) {
                unsigned b0 = __float_as_uint(kcur[(n * 8 + g) * TP2 + kb + t]);
                unsigned b1 = __float_as_uint(kcur[(n * 8 + g) * TP2 + kb + t + 4]);
                mma8(sc[0][n], a[0][0], a[0][1], a[0][2], a[0][3], b0, b1);
                mma8(sc[1][n], a[1][0], a[1][1], a[1][2], a[1][3], b0, b1);
            }
        }

        // Softmax (registers + shfl; exp on MUFU), then stash P
        #pragma unroll
        for (int h = 0; h < 2; h++) {
            float mx0 = -1e30f, mx1 = -1e30f;
            #pragma unroll
            for (int n = 0; n < 8; n++) {
                mx0 = fmaxf(mx0, fmaxf(sc[h][n][0], sc[h][n][1]));
                mx1 = fmaxf(mx1, fmaxf(sc[h][n][2], sc[h][n][3]));
            }
            mx0 = fmaxf(mx0, __shfl_xor_sync(0xffffffffu, mx0, 1));
            mx0 = fmaxf(mx0, __shfl_xor_sync(0xffffffffu, mx0, 2));
            mx1 = fmaxf(mx1, __shfl_xor_sync(0xffffffffu, mx1, 1));
            mx1 = fmaxf(mx1, __shfl_xor_sync(0xffffffffu, mx1, 2));
            float mn0 = fmaxf(m[2 * h], mx0);
            float mn1 = fmaxf(m[2 * h + 1], mx1);
            float f0 = exp2a(m[2 * h] - mn0);
            float f1 = exp2a(m[2 * h + 1] - mn1);
            float s0 = 0.0f, s1 = 0.0f;
            #pragma unroll
            for (int n = 0; n < 8; n++) {
                sc[h][n][0] = tf32r(exp2a(sc[h][n][0] - mn0)); s0 += sc[h][n][0];
                sc[h][n][1] = tf32r(exp2a(sc[h][n][1] - mn0)); s0 += sc[h][n][1];
                sc[h][n][2] = tf32r(exp2a(sc[h][n][2] - mn1)); s1 += sc[h][n][2];
                sc[h][n][3] = tf32r(exp2a(sc[h][n][3] - mn1)); s1 += sc[h][n][3];
            }
            s0 += __shfl_xor_sync(0xffffffffu, s0, 1);
            s0 += __shfl_xor_sync(0xffffffffu, s0, 2);
            s1 += __shfl_xor_sync(0xffffffffu, s1, 1);
            s1 += __shfl_xor_sync(0xffffffffu, s1, 2);
            l[2 * h]     = l[2 * h] * f0 + s0;
            l[2 * h + 1] = l[2 * h + 1] * f1 + s1;
            m[2 * h]     = mn0;
            m[2 * h + 1] = mn1;
            #pragma unroll
            for (int n = 0; n < 8; n++) {
                acc[h][n][0] *= f0; acc[h][n][1] *= f0;
                acc[h][n][2] *= f1; acc[h][n][3] *= f1;
            }
            int rr = r0 + h * 16 + g;
            #pragma unroll
            for (int n = 0; n < 8; n++) {
                *(float2*)&ps[rr * TP2 + n * 8 + 2 * t] =
                    make_float2(sc[h][n][0], sc[h][n][1]);
                *(float2*)&ps[(rr + 8) * TP2 + n * 8 + 2 * t] =
                    make_float2(sc[h][n][2], sc[h][n][3]);
            }
        }
        __syncwarp();

        // Phase C: O += P * V  (warp: 32 rows x 64 cols; V frags reused 2x)
        #pragma unroll
        for (int kk = 0; kk < 8; kk++) {
            int kb = kk * 8;
            unsigned a[2][4];
            #pragma unroll
            for (int h = 0; h < 2; h++) {
                int rr = r0 + h * 16 + g;
                a[h][0] = __float_as_uint(ps[rr * TP2 + kb + t]);
                a[h][1] = __float_as_uint(ps[(rr + 8) * TP2 + kb + t]);
                a[h][2] = __float_as_uint(ps[rr * TP2 + kb + t + 4]);
                a[h][3] = __float_as_uint(ps[(rr + 8) * TP2 + kb + t + 4]);
            }
            #pragma unroll
            for (int n = 0; n < 8; n++) {
                unsigned b0 = __float_as_uint(vcur[(kb + t) * TP2 + n * 8 + g]);
                unsigned b1 = __float_as_uint(vcur[(kb + t + 4) * TP2 + n * 8 + g]);
                mma8(acc[0][n], a[0][0], a[0][1], a[0][2], a[0][3], b0, b1);
                mma8(acc[1][n], a[1][0], a[1][1], a[1][2], a[1][3], b0, b1);
            }
        }
        // next-iter __syncthreads guards K/V buffer and P-slice reuse
    }

    // Epilogue: normalize by l and store
    #pragma unroll
    for (int h = 0; h < 2; h++) {
        int ra = q0 + r0 + h * 16 + g;
        int rb = ra + 8;
        float ia = 1.0f / l[2 * h];
        float ib = 1.0f / l[2 * h + 1];
        #pragma unroll
        for (int n = 0; n < 8; n++) {
            int col = n * 8 + 2 * t;
            *(float2*)&out[((size_t)b * TT + ra) * HD + col] =
                make_float2(acc[h][n][0] * ia, acc[h][n][1] * ia);
            *(float2*)&out[((size_t)b * TT + rb) * HD + col] =
                make_float2(acc[h][n][2] * ib, acc[h][n][3] * ib);
        }
    }
}

// ---------------------------------------------------------------------------
extern "C" void kernel_launch(void* const* d_in, const int* in_sizes, int n_in,
                              void* d_out, int out_size) {
    const float* x      = (const float*)d_in[0];  // [8,2048,1024]
    const float* c_emb  = (const float*)d_in[1];  // [64,64]
    const float* Wq     = (const float*)d_in[2];  // [1024,64]
    const float* Wk     = (const float*)d_in[3];
    const float* Wv     = (const float*)d_in[4];
    const float* gamma  = (const float*)d_in[5];  // [64]
    const float* beta   = (const float*)d_in[6];  // [64]
    float* out          = (float*)d_out;          // [8,2048,64]

    (void)in_sizes; (void)n_in; (void)out_size;

    cudaFuncSetAttribute(attn_kernel,
                         cudaFuncAttributeMaxDynamicSharedMemorySize,
                         ATTN_SMEM_BYTES);

    ln_kernel<<<MM, 64>>>(c_emb, gamma, beta);
    qkv_kernel<<<BT / 128, 256>>>(x, Wq, Wk, Wv);
    dim3 agrid(TT / 128, BB);
    attn_kernel<<<agrid, 128, ATTN_SMEM_BYTES>>>(out);
}